// round 8
// baseline (speedup 1.0000x reference)
#include <cuda_runtime.h>
#include <cuda_fp16.h>
#include <stdint.h>
#include <math.h>

// Problem constants
#define B_   32
#define Q_   20
#define T_   100
#define KDIM 512          // D == H == 512 (GEMM K dim)
#define H_   512
#define N_   (B_*Q_)      // 640 sequences
#define G_   (4*H_)       // 2048 gate columns (interleaved: jp = h*4 + gate)
#define M_   (N_*T_)      // 64000 rows of the x_gates GEMM

#define LDS_   40         // padded smem row stride (fp16 elems)
#define CH     32         // k-chunk
#define NCHUNK (KDIM/CH)  // 16

#define NSTEP_CTAS 128    // 32 j-blocks x 4 n-blocks (1 per SM, wave-1)
#define XG_PER_T   160    // 32 j-blocks x 5 n-blocks per timestep

// step path smem layout (bytes); 2 stages
#define ST_STAGE 35840
#define ST_HLO   12800
#define ST_WHI   25600
#define ST_WLO   30720
#define SMEM_BYTES (ST_STAGE*2)   // 71680

// xg path smem layout (bytes); 2 stages
#define XS_STAGE 30720
#define XS_ALO   10240
#define XS_BHI   20480
#define XS_BLO   25600
#define XS_BIAS  61440            // 64 floats

// ---------------------------------------------------------------------------
// Static device scratch
// ---------------------------------------------------------------------------
__device__ __align__(16) float  g_xg[(size_t)M_ * G_];      // interleaved gate pre-acts
__device__ __align__(16) __half gX_hi[(size_t)M_ * KDIM];
__device__ __align__(16) __half gX_lo[(size_t)M_ * KDIM];
__device__ __align__(16) __half gWih_hi[(size_t)G_ * KDIM]; // interleaved rows
__device__ __align__(16) __half gWih_lo[(size_t)G_ * KDIM];
__device__ __align__(16) __half gWhh_hi[(size_t)G_ * KDIM]; // interleaved rows
__device__ __align__(16) __half gWhh_lo[(size_t)G_ * KDIM];
__device__ float g_biasI[G_];                               // interleaved bih+bhh
__device__ __align__(16) __half g_h_hi[2][(size_t)N_ * H_];
__device__ __align__(16) __half g_h_lo[2][(size_t)N_ * H_];
__device__ float g_c[(size_t)N_ * H_];
__device__ unsigned g_arrive;                               // step grid barrier
__device__ unsigned g_done[T_];                             // xg completion per t

// ---------------------------------------------------------------------------
// PTX helpers
// ---------------------------------------------------------------------------
__device__ __forceinline__ uint32_t smem_u32_of(const void* p) {
    uint32_t a;
    asm("{ .reg .u64 t; cvta.to.shared.u64 t, %1; cvt.u32.u64 %0, t; }" : "=r"(a) : "l"(p));
    return a;
}
__device__ __forceinline__ void cp16(uint32_t dst, const void* src) {
    asm volatile("cp.async.cg.shared.global [%0], [%1], 16;" :: "r"(dst), "l"(src));
}
__device__ __forceinline__ void cp_commit() {
    asm volatile("cp.async.commit_group;" ::: "memory");
}
template<int NN> __device__ __forceinline__ void cp_wait() {
    asm volatile("cp.async.wait_group %0;" :: "n"(NN) : "memory");
}
__device__ __forceinline__ void ldm4(uint32_t addr, uint32_t* r) {
    asm volatile("ldmatrix.sync.aligned.m8n8.x4.shared.b16 {%0,%1,%2,%3}, [%4];"
        : "=r"(r[0]), "=r"(r[1]), "=r"(r[2]), "=r"(r[3]) : "r"(addr));
}
__device__ __forceinline__ void mma16816(float* c, const uint32_t* a, const uint32_t* b) {
    asm volatile("mma.sync.aligned.m16n8k16.row.col.f32.f16.f16.f32 "
        "{%0,%1,%2,%3}, {%4,%5,%6,%7}, {%8,%9}, {%0,%1,%2,%3};"
        : "+f"(c[0]), "+f"(c[1]), "+f"(c[2]), "+f"(c[3])
        : "r"(a[0]), "r"(a[1]), "r"(a[2]), "r"(a[3]), "r"(b[0]), "r"(b[1]));
}
__device__ __forceinline__ void f2split(float x, __half& hi, __half& lo) {
    hi = __float2half_rn(x);
    lo = __float2half_rn(x - __half2float(hi));
}

// ---------------------------------------------------------------------------
// Setup kernels
// ---------------------------------------------------------------------------
__global__ void init_state_kernel() {
    int idx = blockIdx.x * blockDim.x + threadIdx.x;
    if (idx == 0) g_arrive = 0u;
    if (idx < T_) g_done[idx] = 0u;
    if (idx < N_ * H_) {
        g_h_hi[0][idx] = __float2half_rn(0.0f);
        g_h_lo[0][idx] = __float2half_rn(0.0f);
        g_c[idx] = 0.0f;
    }
}

__global__ void conv_x_kernel(const float* __restrict__ X) {
    size_t base = ((size_t)blockIdx.x * blockDim.x + threadIdx.x) * 4;
    if (base < (size_t)M_ * KDIM) {
        float4 v = *(const float4*)(X + base);
        __half h0, l0, h1, l1, h2, l2, h3, l3;
        f2split(v.x, h0, l0); f2split(v.y, h1, l1);
        f2split(v.z, h2, l2); f2split(v.w, h3, l3);
        gX_hi[base + 0] = h0; gX_hi[base + 1] = h1; gX_hi[base + 2] = h2; gX_hi[base + 3] = h3;
        gX_lo[base + 0] = l0; gX_lo[base + 1] = l1; gX_lo[base + 2] = l2; gX_lo[base + 3] = l3;
    }
}

__global__ void conv_w_kernel(const float* __restrict__ Wih,
                              const float* __restrict__ Whh,
                              const float* __restrict__ bih,
                              const float* __restrict__ bhh) {
    int jp = blockIdx.x;                 // interleaved dst row 0..2047
    int gate = jp & 3, h = jp >> 2;
    int j = gate * H_ + h;               // source row
    const float* si = Wih + (size_t)j * KDIM;
    const float* sh = Whh + (size_t)j * KDIM;
    for (int k = threadIdx.x; k < KDIM; k += blockDim.x) {
        __half hi, lo;
        f2split(si[k], hi, lo);
        gWih_hi[(size_t)jp * KDIM + k] = hi; gWih_lo[(size_t)jp * KDIM + k] = lo;
        f2split(sh[k], hi, lo);
        gWhh_hi[(size_t)jp * KDIM + k] = hi; gWhh_lo[(size_t)jp * KDIM + k] = lo;
    }
    if (threadIdx.x == 0) g_biasI[jp] = bih[j] + bhh[j];
}

// ---------------------------------------------------------------------------
// Step grid barrier (128 step CTAs; all co-resident from wave 1)
// ---------------------------------------------------------------------------
__device__ __forceinline__ void grid_barrier(int tid, unsigned target) {
    __threadfence();
    __syncthreads();
    if (tid == 0) {
        atomicAdd(&g_arrive, 1u);
        unsigned v;
        do {
            asm volatile("ld.volatile.global.u32 %0, [%1];" : "=r"(v) : "l"(&g_arrive));
        } while (v < target);
        __threadfence();
    }
    __syncthreads();
}

// ---------------------------------------------------------------------------
// FUSED kernel: bids 0..127 = persistent LSTM step CTAs;
//               bids 128..16127 = xg tiles, t-major, gated via g_done[t].
// ---------------------------------------------------------------------------
__global__ __launch_bounds__(256, 2)
void fused_kernel(float* __restrict__ out) {
    extern __shared__ char smem[];
    const uint32_t sb = smem_u32_of(smem);
    const int tid = threadIdx.x;
    const int lane = tid & 31, wid = tid >> 5;
    const int bid = blockIdx.x;

    if (bid < NSTEP_CTAS) {
        // ================= persistent LSTM step path =================
        const int jb = bid & 31, nc = bid >> 5;
        const int j0 = jb * 64;            // interleaved gate-col base
        const int hb = jb * 16;            // h-col base
        const int n0 = nc * 160;           // row base
        const int wn = wid & 3, wm = wid >> 2;
        const int a_row = wm * 80 + (lane & 15);
        const int a_col = (lane >> 4) * 8;
        const int b_row = wn * 16 + ((lane >> 4) << 3) + (lane & 7);
        const int b_col = ((lane >> 3) & 1) * 8;
        const __half* Wh = gWhh_hi + (size_t)j0 * KDIM;
        const __half* Wl = gWhh_lo + (size_t)j0 * KDIM;
        float* Cs = (float*)smem;

        #pragma unroll 1
        for (int t = 0; t < T_; ++t) {
            const int cur = t & 1, nxt = cur ^ 1;
            const __half* Hh = g_h_hi[cur] + (size_t)n0 * H_;
            const __half* Hl = g_h_lo[cur] + (size_t)n0 * H_;

            float acc[5][2][4];
            #pragma unroll
            for (int a = 0; a < 5; ++a)
                #pragma unroll
                for (int b = 0; b < 2; ++b)
                    #pragma unroll
                    for (int d = 0; d < 4; ++d) acc[a][b][d] = 0.0f;

            #define LOADS(stg, kc) do {                                         \
                uint32_t _b = sb + (uint32_t)(stg) * ST_STAGE;                   \
                _Pragma("unroll")                                                \
                for (int u = tid; u < 640; u += 256) {                           \
                    int r_ = u >> 2, cg_ = (u & 3) * 8;                          \
                    uint32_t d_ = _b + (uint32_t)(r_ * LDS_ + cg_) * 2;          \
                    size_t g_ = (size_t)r_ * H_ + (kc) + cg_;                    \
                    cp16(d_,          Hh + g_);                                  \
                    cp16(d_ + ST_HLO, Hl + g_);                                  \
                }                                                                \
                _Pragma("unroll")                                                \
                for (int u = tid; u < 256; u += 256) {                           \
                    int r_ = u >> 2, cg_ = (u & 3) * 8;                          \
                    uint32_t d_ = _b + ST_WHI + (uint32_t)(r_ * LDS_ + cg_) * 2; \
                    size_t g_ = (size_t)r_ * KDIM + (kc) + cg_;                  \
                    cp16(d_,                   Wh + g_);                         \
                    cp16(d_ + (ST_WLO-ST_WHI), Wl + g_);                         \
                }                                                                \
            } while (0)

            LOADS(0, 0);
            cp_commit();

            #pragma unroll 1
            for (int c = 0; c < NCHUNK; ++c) {
                cp_wait<0>();             // stage c ready
                __syncthreads();          // all warps done with previous stage
                if (c + 1 < NCHUNK) LOADS((c + 1) & 1, (c + 1) * CH);
                cp_commit();

                const uint32_t base = sb + (uint32_t)(c & 1) * ST_STAGE;
                #pragma unroll
                for (int kk = 0; kk < CH; kk += 16) {
                    uint32_t ra[5][4], rl[5][4], rbh[4], rbl[4];
                    #pragma unroll
                    for (int mi = 0; mi < 5; ++mi) {
                        uint32_t aa = base + (uint32_t)((a_row + mi * 16) * LDS_ + kk + a_col) * 2;
                        ldm4(aa, ra[mi]);
                        ldm4(aa + ST_HLO, rl[mi]);
                    }
                    uint32_t ba = base + ST_WHI + (uint32_t)(b_row * LDS_ + kk + b_col) * 2;
                    ldm4(ba, rbh);
                    ldm4(ba + (ST_WLO - ST_WHI), rbl);
                    #pragma unroll
                    for (int mi = 0; mi < 5; ++mi) {
                        #pragma unroll
                        for (int b8 = 0; b8 < 2; ++b8) {
                            const uint32_t* bh = &rbh[b8 * 2];
                            const uint32_t* bl = &rbl[b8 * 2];
                            mma16816(acc[mi][b8], ra[mi], bh);   // hi*hi
                            mma16816(acc[mi][b8], ra[mi], bl);   // hi*lo
                            mma16816(acc[mi][b8], rl[mi], bh);   // lo*hi
                        }
                    }
                }
            }
            #undef LOADS

            // stage C tile [160][68] in smem (reuses pipeline stages)
            __syncthreads();
            #pragma unroll
            for (int mi = 0; mi < 5; ++mi) {
                #pragma unroll
                for (int b8 = 0; b8 < 2; ++b8) {
                    const int r = wm * 80 + mi * 16 + (lane >> 2);
                    const int cc = wn * 16 + b8 * 8 + (lane & 3) * 2;
                    *(float2*)&Cs[r * 68 + cc]       = make_float2(acc[mi][b8][0], acc[mi][b8][1]);
                    *(float2*)&Cs[(r + 8) * 68 + cc] = make_float2(acc[mi][b8][2], acc[mi][b8][3]);
                }
            }

            // gate on xg availability for this t
            if (tid == 0) {
                unsigned v;
                do {
                    asm volatile("ld.volatile.global.u32 %0, [%1];" : "=r"(v) : "l"(&g_done[t]));
                } while (v < XG_PER_T);
                __threadfence();
            }
            __syncthreads();

            // fused LSTM cell update: 10 cells/thread
            const bool last = (t == T_ - 1);
            const int hl = tid & 15;
            const int rg = tid >> 4;
            #pragma unroll
            for (int e = 0; e < 10; ++e) {
                const int r = rg + e * 16;
                const int gn = n0 + r;
                float4 cg = *(const float4*)&Cs[r * 68 + hl * 4];
                float4 xv = *(const float4*)(g_xg + ((size_t)gn * T_ + t) * G_ + j0 + hl * 4);
                float ig = cg.x + xv.x, fg = cg.y + xv.y;
                float gg = cg.z + xv.z, og = cg.w + xv.w;

                float is = 1.0f / (1.0f + __expf(-ig));
                float fs = 1.0f / (1.0f + __expf(-fg));
                float gt = tanhf(gg);
                float os = 1.0f / (1.0f + __expf(-og));

                const size_t ci = (size_t)gn * H_ + hb + hl;
                float c = fs * g_c[ci] + is * gt;
                g_c[ci] = c;
                float hv = os * tanhf(c);
                if (last) {
                    out[ci] = hv;
                } else {
                    __half hi, lo;
                    f2split(hv, hi, lo);
                    g_h_hi[nxt][ci] = hi;
                    g_h_lo[nxt][ci] = lo;
                }
            }

            if (t + 1 < T_)
                grid_barrier(tid, (unsigned)NSTEP_CTAS * (unsigned)(t + 1));
        }
    } else {
        // ================= xg tile path (t-major) =================
        const int q = bid - NSTEP_CTAS;
        const int t = q / XG_PER_T;
        const int w = q % XG_PER_T;
        const int jb = w & 31, nb = w >> 5;   // jb 0..31, nb 0..4
        const int j0 = jb * 64;
        const int n0 = nb * 128;
        const int mw = (wid & 1) * 64;
        const int wn = wid >> 1;
        const int a_row = mw + (lane & 15);
        const int a_col = (lane >> 4) * 8;
        const int b_row = wn * 16 + ((lane >> 4) << 3) + (lane & 7);
        const int b_col = ((lane >> 3) & 1) * 8;

        const size_t APITCH = (size_t)T_ * KDIM;
        const __half* Ah = gX_hi + ((size_t)n0 * T_ + t) * KDIM;
        const __half* Al = gX_lo + ((size_t)n0 * T_ + t) * KDIM;
        const __half* Bh = gWih_hi + (size_t)j0 * KDIM;
        const __half* Bl = gWih_lo + (size_t)j0 * KDIM;

        if (tid < 64) ((float*)(smem + XS_BIAS))[tid] = g_biasI[j0 + tid];

        float acc[4][2][4];
        #pragma unroll
        for (int a = 0; a < 4; ++a)
            #pragma unroll
            for (int b = 0; b < 2; ++b)
                #pragma unroll
                for (int d = 0; d < 4; ++d) acc[a][b][d] = 0.0f;

        #define LOADX(stg, kc) do {                                         \
            uint32_t _b = sb + (uint32_t)(stg) * XS_STAGE;                   \
            _Pragma("unroll")                                                \
            for (int u = tid; u < 512; u += 256) {                           \
                int r_ = u >> 2, cg_ = (u & 3) * 8;                          \
                uint32_t d_ = _b + (uint32_t)(r_ * LDS_ + cg_) * 2;          \
                size_t g_ = (size_t)r_ * APITCH + (kc) + cg_;                \
                cp16(d_,          Ah + g_);                                  \
                cp16(d_ + XS_ALO, Al + g_);                                  \
            }                                                                \
            _Pragma("unroll")                                                \
            for (int u = tid; u < 256; u += 256) {                           \
                int r_ = u >> 2, cg_ = (u & 3) * 8;                          \
                uint32_t d_ = _b + XS_BHI + (uint32_t)(r_ * LDS_ + cg_) * 2; \
                size_t g_ = (size_t)r_ * KDIM + (kc) + cg_;                  \
                cp16(d_,                   Bh + g_);                         \
                cp16(d_ + (XS_BLO-XS_BHI), Bl + g_);                         \
            }                                                                \
        } while (0)

        LOADX(0, 0);
        cp_commit();

        #pragma unroll 1
        for (int c = 0; c < NCHUNK; ++c) {
            cp_wait<0>();
            __syncthreads();
            if (c + 1 < NCHUNK) LOADX((c + 1) & 1, (c + 1) * CH);
            cp_commit();

            const uint32_t base = sb + (uint32_t)(c & 1) * XS_STAGE;
            #pragma unroll
            for (int kk = 0; kk < CH; kk += 16) {
                uint32_t ra[4][4], rl[4][4], rbh[4], rbl[4];
                #pragma unroll
                for (int mi = 0; mi < 4; ++mi) {
                    uint32_t aa = base + (uint32_t)((a_row + mi * 16) * LDS_ + kk + a_col) * 2;
                    ldm4(aa, ra[mi]);
                    ldm4(aa + XS_ALO, rl[mi]);
                }
                uint32_t ba = base + XS_BHI + (uint32_t)(b_row * LDS_ + kk + b_col) * 2;
                ldm4(ba, rbh);
                ldm4(ba + (XS_BLO - XS_BHI), rbl);
                #pragma unroll
                for (int mi = 0; mi < 4; ++mi) {
                    #pragma unroll
                    for (int b8 = 0; b8 < 2; ++b8) {
                        const uint32_t* bh = &rbh[b8 * 2];
                        const uint32_t* bl = &rbl[b8 * 2];
                        mma16816(acc[mi][b8], ra[mi], bh);
                        mma16816(acc[mi][b8], ra[mi], bl);
                        mma16816(acc[mi][b8], rl[mi], bh);
                    }
                }
            }
        }
        #undef LOADX

        __syncthreads();
        const float* biasS = (const float*)(smem + XS_BIAS);
        #pragma unroll
        for (int mi = 0; mi < 4; ++mi) {
            #pragma unroll
            for (int h2 = 0; h2 < 2; ++h2) {
                const int r = mw + mi * 16 + (lane >> 2) + h2 * 8;
                float* dst = g_xg + ((size_t)(n0 + r) * T_ + t) * G_ + j0;
                #pragma unroll
                for (int b8 = 0; b8 < 2; ++b8) {
                    const int cc = wn * 16 + b8 * 8 + (lane & 3) * 2;
                    float2 v = make_float2(acc[mi][b8][h2 * 2 + 0] + biasS[cc],
                                           acc[mi][b8][h2 * 2 + 1] + biasS[cc + 1]);
                    *(float2*)(dst + cc) = v;
                }
            }
        }

        // publish completion for this t
        __threadfence();
        __syncthreads();
        if (tid == 0) atomicAdd(&g_done[t], 1u);
    }
}

// ---------------------------------------------------------------------------
// Launch
// ---------------------------------------------------------------------------
extern "C" void kernel_launch(void* const* d_in, const int* in_sizes, int n_in,
                              void* d_out, int out_size)
{
    const float* X   = (const float*)d_in[0];   // [B,Q,T,D] == [N*T, D]
    const float* Wih = (const float*)d_in[1];   // [4H, D]
    const float* Whh = (const float*)d_in[2];   // [4H, H]
    const float* bih = (const float*)d_in[3];   // [4H]
    const float* bhh = (const float*)d_in[4];   // [4H]
    float* out = (float*)d_out;                 // [B,Q,H] == [N, H]

    cudaFuncSetAttribute(fused_kernel, cudaFuncAttributeMaxDynamicSharedMemorySize, SMEM_BYTES);

    init_state_kernel<<<(N_ * H_ + 255) / 256, 256>>>();
    conv_x_kernel<<<(int)(((size_t)M_ * KDIM / 4 + 255) / 256), 256>>>(X);
    conv_w_kernel<<<G_, 256>>>(Wih, Whh, bih, bhh);

    fused_kernel<<<NSTEP_CTAS + T_ * XG_PER_T, 256, SMEM_BYTES>>>(out);
}

// round 10
// speedup vs baseline: 1.3100x; 1.3100x over previous
#include <cuda_runtime.h>
#include <cuda_fp16.h>
#include <stdint.h>
#include <math.h>

// Problem constants
#define B_   32
#define Q_   20
#define T_   100
#define KDIM 512          // D == H == 512 (GEMM K dim)
#define H_   512
#define N_   (B_*Q_)      // 640 sequences
#define G_   (4*H_)       // 2048 gate columns (interleaved: jp = h*4 + gate)
#define M_   (N_*T_)      // 64000 rows of the x_gates GEMM

#define LDS_   40         // xg smem row stride (fp16 elems)
#define CH     32         // xg k-chunk
#define NCHUNK (KDIM/CH)  // 16

// step kernel: CH=64 k-chunks, stride 72
#define SCH    64
#define SNCH   (KDIM/SCH) // 8
#define SSTR   72         // 64 + 8 pad

// ---------------------------------------------------------------------------
// Static device scratch
// ---------------------------------------------------------------------------
__device__ __align__(16) float  g_xg[(size_t)M_ * G_];      // interleaved gate pre-acts
__device__ __align__(16) __half gX_hi[(size_t)M_ * KDIM];
__device__ __align__(16) __half gX_lo[(size_t)M_ * KDIM];
__device__ __align__(16) __half gWih_hi[(size_t)G_ * KDIM]; // interleaved rows
__device__ __align__(16) __half gWih_lo[(size_t)G_ * KDIM];
__device__ __align__(16) __half gWhh_hi[(size_t)G_ * KDIM]; // interleaved rows
__device__ __align__(16) __half gWhh_lo[(size_t)G_ * KDIM];
__device__ float g_biasI[G_];                               // interleaved bih+bhh
__device__ __align__(16) __half g_h_hi[2][(size_t)N_ * H_];
__device__ __align__(16) __half g_h_lo[2][(size_t)N_ * H_];
__device__ float g_c[(size_t)N_ * H_];

// ---------------------------------------------------------------------------
// PTX helpers
// ---------------------------------------------------------------------------
__device__ __forceinline__ uint32_t smem_u32_of(const void* p) {
    uint32_t a;
    asm("{ .reg .u64 t; cvta.to.shared.u64 t, %1; cvt.u32.u64 %0, t; }" : "=r"(a) : "l"(p));
    return a;
}
__device__ __forceinline__ void cp16(uint32_t dst, const void* src) {
    asm volatile("cp.async.cg.shared.global [%0], [%1], 16;" :: "r"(dst), "l"(src));
}
__device__ __forceinline__ void cp_commit() {
    asm volatile("cp.async.commit_group;" ::: "memory");
}
template<int NN> __device__ __forceinline__ void cp_wait() {
    asm volatile("cp.async.wait_group %0;" :: "n"(NN) : "memory");
}
__device__ __forceinline__ void ldm4(uint32_t addr, uint32_t* r) {
    asm volatile("ldmatrix.sync.aligned.m8n8.x4.shared.b16 {%0,%1,%2,%3}, [%4];"
        : "=r"(r[0]), "=r"(r[1]), "=r"(r[2]), "=r"(r[3]) : "r"(addr));
}
__device__ __forceinline__ void mma16816(float* c, const uint32_t* a, const uint32_t* b) {
    asm volatile("mma.sync.aligned.m16n8k16.row.col.f32.f16.f16.f32 "
        "{%0,%1,%2,%3}, {%4,%5,%6,%7}, {%8,%9}, {%0,%1,%2,%3};"
        : "+f"(c[0]), "+f"(c[1]), "+f"(c[2]), "+f"(c[3])
        : "r"(a[0]), "r"(a[1]), "r"(a[2]), "r"(a[3]), "r"(b[0]), "r"(b[1]));
}
__device__ __forceinline__ void f2split(float x, __half& hi, __half& lo) {
    hi = __float2half_rn(x);
    lo = __float2half_rn(x - __half2float(hi));
}

// ---------------------------------------------------------------------------
// Setup kernels
// ---------------------------------------------------------------------------
__global__ void init_state_kernel() {
    int idx = blockIdx.x * blockDim.x + threadIdx.x;
    if (idx < N_ * H_) {
        g_h_hi[0][idx] = __float2half_rn(0.0f);
        g_h_lo[0][idx] = __float2half_rn(0.0f);
        g_c[idx] = 0.0f;
    }
}

__global__ void conv_x_kernel(const float* __restrict__ X) {
    size_t base = ((size_t)blockIdx.x * blockDim.x + threadIdx.x) * 4;
    if (base < (size_t)M_ * KDIM) {
        float4 v = *(const float4*)(X + base);
        __half h0, l0, h1, l1, h2, l2, h3, l3;
        f2split(v.x, h0, l0); f2split(v.y, h1, l1);
        f2split(v.z, h2, l2); f2split(v.w, h3, l3);
        gX_hi[base + 0] = h0; gX_hi[base + 1] = h1; gX_hi[base + 2] = h2; gX_hi[base + 3] = h3;
        gX_lo[base + 0] = l0; gX_lo[base + 1] = l1; gX_lo[base + 2] = l2; gX_lo[base + 3] = l3;
    }
}

__global__ void conv_w_kernel(const float* __restrict__ Wih,
                              const float* __restrict__ Whh,
                              const float* __restrict__ bih,
                              const float* __restrict__ bhh) {
    int jp = blockIdx.x;                 // interleaved dst row 0..2047
    int gate = jp & 3, h = jp >> 2;
    int j = gate * H_ + h;               // source row
    const float* si = Wih + (size_t)j * KDIM;
    const float* sh = Whh + (size_t)j * KDIM;
    for (int k = threadIdx.x; k < KDIM; k += blockDim.x) {
        __half hi, lo;
        f2split(si[k], hi, lo);
        gWih_hi[(size_t)jp * KDIM + k] = hi; gWih_lo[(size_t)jp * KDIM + k] = lo;
        f2split(sh[k], hi, lo);
        gWhh_hi[(size_t)jp * KDIM + k] = hi; gWhh_lo[(size_t)jp * KDIM + k] = lo;
    }
    if (threadIdx.x == 0) g_biasI[jp] = bih[j] + bhh[j];
}

// ---------------------------------------------------------------------------
// xg chunk loader + mainloop (as R6)
// ---------------------------------------------------------------------------
template<int MT, int NT>
__device__ __forceinline__ void load_chunk(
    uint32_t sbase,
    const __half* __restrict__ Ah, const __half* __restrict__ Al,
    const __half* __restrict__ Bh, const __half* __restrict__ Bl,
    int kc, int tid)
{
    #pragma unroll
    for (int u = tid; u < MT * 4; u += 256) {
        int r = u >> 2, c = (u & 3) * 8;
        uint32_t d = sbase + (uint32_t)(r * LDS_ + c) * 2;
        const size_t go = (size_t)r * KDIM + kc + c;
        cp16(d,                 Ah + go);
        cp16(d + MT * LDS_ * 2, Al + go);
    }
    #pragma unroll
    for (int u = tid; u < NT * 4; u += 256) {
        int r = u >> 2, c = (u & 3) * 8;
        uint32_t d = sbase + (uint32_t)(2 * MT * LDS_ + r * LDS_ + c) * 2;
        const size_t go = (size_t)r * KDIM + kc + c;
        cp16(d,                 Bh + go);
        cp16(d + NT * LDS_ * 2, Bl + go);
    }
}

template<int MI, int NJ, int S>
__device__ __forceinline__ void mma_mainloop(
    uint32_t sb,
    const __half* __restrict__ Ah, const __half* __restrict__ Al,
    const __half* __restrict__ Bh, const __half* __restrict__ Bl,
    float acc[MI][NJ * 2][4], int tid)
{
    const int MT = MI * 32;
    const int NT = NJ * 64;
    const int STAGE_B = (2 * MT * LDS_ + 2 * NT * LDS_) * 2;
    const int lane = tid & 31, wid = tid >> 5;
    const int mw = (wid & 1) * (MI * 16);
    const int nw = (wid >> 1) * (NJ * 16);

    const int a_row = mw + (lane & 15);
    const int a_col = (lane >> 4) * 8;
    const int b_row = nw + ((lane >> 4) << 3) + (lane & 7);
    const int b_col = ((lane >> 3) & 1) * 8;

    #pragma unroll
    for (int p = 0; p < S - 1; ++p) {
        load_chunk<MT, NT>(sb + p * STAGE_B, Ah, Al, Bh, Bl, p * CH, tid);
        cp_commit();
    }

    #pragma unroll 1
    for (int c = 0; c < NCHUNK; ++c) {
        if (c + S - 1 < NCHUNK)
            load_chunk<MT, NT>(sb + ((c + S - 1) % S) * STAGE_B, Ah, Al, Bh, Bl,
                               (c + S - 1) * CH, tid);
        cp_commit();
        cp_wait<S - 1>();
        __syncthreads();

        const uint32_t base = sb + (c % S) * STAGE_B;
        #pragma unroll
        for (int kk = 0; kk < CH; kk += 16) {
            uint32_t ra[MI][4], rl[MI][4];
            uint32_t rbh[NJ][4], rbl[NJ][4];
            #pragma unroll
            for (int mi = 0; mi < MI; ++mi) {
                uint32_t aa = base + (uint32_t)((a_row + mi * 16) * LDS_ + kk + a_col) * 2;
                ldm4(aa, ra[mi]);
                ldm4(aa + MT * LDS_ * 2, rl[mi]);
            }
            #pragma unroll
            for (int nj = 0; nj < NJ; ++nj) {
                uint32_t ba = base + (uint32_t)(2 * MT * LDS_ + (b_row + nj * 16) * LDS_ + kk + b_col) * 2;
                ldm4(ba, rbh[nj]);
                ldm4(ba + NT * LDS_ * 2, rbl[nj]);
            }
            #pragma unroll
            for (int mi = 0; mi < MI; ++mi) {
                #pragma unroll
                for (int b8 = 0; b8 < NJ * 2; ++b8) {
                    const uint32_t* bh = &rbh[b8 >> 1][(b8 & 1) * 2];
                    const uint32_t* bl = &rbl[b8 >> 1][(b8 & 1) * 2];
                    mma16816(acc[mi][b8], ra[mi], bh);
                    mma16816(acc[mi][b8], ra[mi], bl);
                    mma16816(acc[mi][b8], rl[mi], bh);
                }
            }
        }
        __syncthreads();
    }
}

// ---------------------------------------------------------------------------
// x_gates GEMM: 128x128 tile, grid (16, 500), 2-stage, 2 CTAs/SM (as R6).
// ---------------------------------------------------------------------------
#define XG_STAGE ((2*128*LDS_ + 2*128*LDS_) * 2)         // 40960 B
#define XG_SMEM  (XG_STAGE * 2)                          // 81920 B

__global__ __launch_bounds__(256, 2)
void xg_mma_kernel() {
    extern __shared__ char smem[];
    const uint32_t sb = smem_u32_of(smem);
    __shared__ float bias_s[128];
    const int tid = threadIdx.x;
    const int j0 = blockIdx.x * 128;
    const int m0 = blockIdx.y * 128;
    if (tid < 128) bias_s[tid] = g_biasI[j0 + tid];

    float acc[4][4][4];
    #pragma unroll
    for (int a = 0; a < 4; ++a)
        #pragma unroll
        for (int b = 0; b < 4; ++b)
            #pragma unroll
            for (int d = 0; d < 4; ++d) acc[a][b][d] = 0.0f;

    mma_mainloop<4, 2, 2>(sb,
        gX_hi   + (size_t)m0 * KDIM, gX_lo   + (size_t)m0 * KDIM,
        gWih_hi + (size_t)j0 * KDIM, gWih_lo + (size_t)j0 * KDIM,
        acc, tid);

    const int lane = tid & 31, wid = tid >> 5;
    const int mw = (wid & 1) * 64, nw = (wid >> 1) * 32;
    #pragma unroll
    for (int mi = 0; mi < 4; ++mi) {
        #pragma unroll
        for (int h2 = 0; h2 < 2; ++h2) {
            const int r = m0 + mw + mi * 16 + (lane >> 2) + h2 * 8;
            float* dst = g_xg + (size_t)r * G_ + j0;
            #pragma unroll
            for (int ni = 0; ni < 4; ++ni) {
                const int cc = nw + ni * 8 + (lane & 3) * 2;
                float2 v = make_float2(acc[mi][ni][h2 * 2 + 0] + bias_s[cc],
                                       acc[mi][ni][h2 * 2 + 1] + bias_s[cc + 1]);
                *(float2*)(dst + cc) = v;
            }
        }
    }
}

// ---------------------------------------------------------------------------
// Step kernel body, templated on row count MT (96 or 64).
// CTA tile: MT rows x 64 gate cols. 8 warps 2m x 4n; MI = MT/32; NJ = 1.
// CH=64, 2-stage double buffer, stride 72.
// Stage layout (elems): Hhi[MT*72] Hlo[MT*72] Whi[64*72] Wlo[64*72]
// ---------------------------------------------------------------------------
#define STEP_SMEM 92160   // 2 stages of the MT=96 layout (worst case)

template<int MT>
__device__ __forceinline__ void step_body(
    char* smem, uint32_t sb, int tid, int j0, int hb, int n0, int t,
    float* __restrict__ out)
{
    const int MI = MT / 32;
    const int STAGE_E = 2 * MT * SSTR + 2 * 64 * SSTR;   // elems per stage
    const int STAGE_B = STAGE_E * 2;                     // bytes
    const int lane = tid & 31, wid = tid >> 5;
    const int wm = wid & 1, wn = wid >> 1;

    const int cur = t & 1, nxt = cur ^ 1;
    const __half* Hh = g_h_hi[cur] + (size_t)n0 * H_;
    const __half* Hl = g_h_lo[cur] + (size_t)n0 * H_;
    const __half* Wh = gWhh_hi + (size_t)j0 * KDIM;
    const __half* Wl = gWhh_lo + (size_t)j0 * KDIM;

    const int a_row = wm * (MI * 16) + (lane & 15);
    const int a_col = (lane >> 4) * 8;
    const int b_row = wn * 16 + ((lane >> 4) << 3) + (lane & 7);
    const int b_col = ((lane >> 3) & 1) * 8;

    float acc[MI > 2 ? 3 : 2][2][4];
    #pragma unroll
    for (int a = 0; a < MI; ++a)
        #pragma unroll
        for (int b = 0; b < 2; ++b)
            #pragma unroll
            for (int d = 0; d < 4; ++d) acc[a][b][d] = 0.0f;

    // chunk loader: MT rows h (hi+lo) + 64 rows W (hi+lo), 64 k each
    #define SLOAD(stg, kc) do {                                              \
        uint32_t _b = sb + (uint32_t)(stg) * STAGE_B;                        \
        _Pragma("unroll")                                                    \
        for (int u = tid; u < MT * 8; u += 256) {                            \
            int r_ = u >> 3, cg_ = (u & 7) * 8;                              \
            uint32_t d_ = _b + (uint32_t)(r_ * SSTR + cg_) * 2;              \
            size_t g_ = (size_t)r_ * H_ + (kc) + cg_;                        \
            cp16(d_,                 Hh + g_);                               \
            cp16(d_ + MT * SSTR * 2, Hl + g_);                               \
        }                                                                    \
        _Pragma("unroll")                                                    \
        for (int u = tid; u < 512; u += 256) {                               \
            int r_ = u >> 3, cg_ = (u & 7) * 8;                              \
            uint32_t d_ = _b + (uint32_t)(2 * MT * SSTR + r_ * SSTR + cg_) * 2; \
            size_t g_ = (size_t)r_ * KDIM + (kc) + cg_;                      \
            cp16(d_,                 Wh + g_);                               \
            cp16(d_ + 64 * SSTR * 2, Wl + g_);                               \
        }                                                                    \
    } while (0)

    SLOAD(0, 0);
    cp_commit();

    #pragma unroll 1
    for (int c = 0; c < SNCH; ++c) {
        if (c + 1 < SNCH) {
            SLOAD((c + 1) & 1, (c + 1) * SCH);
            cp_commit();
            cp_wait<1>();
        } else {
            cp_wait<0>();
        }
        __syncthreads();

        const uint32_t base = sb + (uint32_t)(c & 1) * STAGE_B;
        #pragma unroll
        for (int kk = 0; kk < SCH; kk += 16) {
            uint32_t ra[MI > 2 ? 3 : 2][4], rl[MI > 2 ? 3 : 2][4], rbh[4], rbl[4];
            #pragma unroll
            for (int mi = 0; mi < MI; ++mi) {
                uint32_t aa = base + (uint32_t)((a_row + mi * 16) * SSTR + kk + a_col) * 2;
                ldm4(aa, ra[mi]);
                ldm4(aa + MT * SSTR * 2, rl[mi]);
            }
            uint32_t ba = base + (uint32_t)(2 * MT * SSTR + (b_row) * SSTR + kk + b_col) * 2;
            ldm4(ba, rbh);
            ldm4(ba + 64 * SSTR * 2, rbl);
            #pragma unroll
            for (int mi = 0; mi < MI; ++mi) {
                #pragma unroll
                for (int b8 = 0; b8 < 2; ++b8) {
                    const uint32_t* bhp = &rbh[b8 * 2];
                    const uint32_t* blp = &rbl[b8 * 2];
                    mma16816(acc[mi][b8], ra[mi], bhp);   // hi*hi
                    mma16816(acc[mi][b8], ra[mi], blp);   // hi*lo
                    mma16816(acc[mi][b8], rl[mi], bhp);   // lo*hi
                }
            }
        }
        __syncthreads();
    }
    #undef SLOAD

    // stage C tile [MT][68] in smem
    float* Cs = (float*)smem;
    #pragma unroll
    for (int mi = 0; mi < MI; ++mi) {
        #pragma unroll
        for (int b8 = 0; b8 < 2; ++b8) {
            const int r = wm * (MI * 16) + mi * 16 + (lane >> 2);
            const int cc = wn * 16 + b8 * 8 + (lane & 3) * 2;
            *(float2*)&Cs[r * 68 + cc]       = make_float2(acc[mi][b8][0], acc[mi][b8][1]);
            *(float2*)&Cs[(r + 8) * 68 + cc] = make_float2(acc[mi][b8][2], acc[mi][b8][3]);
        }
    }
    __syncthreads();

    // fused LSTM cell update: MT/16 cells per thread
    const bool last = (t == T_ - 1);
    const int hl = tid & 15;
    const int rg = tid >> 4;
    #pragma unroll
    for (int e = 0; e < MT / 16; ++e) {
        const int r = rg + e * 16;
        const int gn = n0 + r;
        float4 cg = *(const float4*)&Cs[r * 68 + hl * 4];
        float4 xv = *(const float4*)(g_xg + ((size_t)gn * T_ + t) * G_ + j0 + hl * 4);
        float ig = cg.x + xv.x, fg = cg.y + xv.y;
        float gg = cg.z + xv.z, og = cg.w + xv.w;

        float is = 1.0f / (1.0f + __expf(-ig));
        float fs = 1.0f / (1.0f + __expf(-fg));
        float gt = tanhf(gg);
        float os = 1.0f / (1.0f + __expf(-og));

        const size_t ci = (size_t)gn * H_ + hb + hl;
        float c = fs * g_c[ci] + is * gt;
        g_c[ci] = c;
        float hv = os * tanhf(c);
        if (last) {
            out[ci] = hv;
        } else {
            __half hi, lo;
            f2split(hv, hi, lo);
            g_h_hi[nxt][ci] = hi;
            g_h_lo[nxt][ci] = lo;
        }
    }
}

// ---------------------------------------------------------------------------
// Step kernel: 288 CTAs = 32 jb x 9 row-tiles (2x96 + 7x64 rows), nt-major
// bids so classic placement pairs 96-row CTAs with 64-row CTAs on one SM.
// Single wave at 2 CTAs/SM (288 <= 296).
// ---------------------------------------------------------------------------
__global__ __launch_bounds__(256, 2)
void step_mma_kernel(float* __restrict__ out, int t) {
    extern __shared__ char smem[];
    const uint32_t sb = smem_u32_of(smem);
    const int tid = threadIdx.x;
    const int bid = blockIdx.x;
    const int nt = bid >> 5;          // 0..8 (row tile)
    const int jb = bid & 31;          // 0..31 (col block)
    const int j0 = jb * 64;
    const int hb = jb * 16;

    if (nt < 2) {
        step_body<96>(smem, sb, tid, j0, hb, nt * 96, t, out);
    } else {
        step_body<64>(smem, sb, tid, j0, hb, 192 + (nt - 2) * 64, t, out);
    }
}

// ---------------------------------------------------------------------------
// Launch
// ---------------------------------------------------------------------------
extern "C" void kernel_launch(void* const* d_in, const int* in_sizes, int n_in,
                              void* d_out, int out_size)
{
    const float* X   = (const float*)d_in[0];   // [B,Q,T,D] == [N*T, D]
    const float* Wih = (const float*)d_in[1];   // [4H, D]
    const float* Whh = (const float*)d_in[2];   // [4H, H]
    const float* bih = (const float*)d_in[3];   // [4H]
    const float* bhh = (const float*)d_in[4];   // [4H]
    float* out = (float*)d_out;                 // [B,Q,H] == [N, H]

    cudaFuncSetAttribute(xg_mma_kernel,   cudaFuncAttributeMaxDynamicSharedMemorySize, XG_SMEM);
    cudaFuncSetAttribute(step_mma_kernel, cudaFuncAttributeMaxDynamicSharedMemorySize, STEP_SMEM);

    init_state_kernel<<<(N_ * H_ + 255) / 256, 256>>>();
    conv_x_kernel<<<(int)(((size_t)M_ * KDIM / 4 + 255) / 256), 256>>>(X);
    conv_w_kernel<<<G_, 256>>>(Wih, Whh, bih, bhh);

    xg_mma_kernel<<<dim3(G_ / 128, M_ / 128), 256, XG_SMEM>>>();

    for (int t = 0; t < T_; ++t) {
        step_mma_kernel<<<288, 256, STEP_SMEM>>>(out, t);
    }
}

// round 11
// speedup vs baseline: 1.4761x; 1.1268x over previous
#include <cuda_runtime.h>
#include <cuda_fp16.h>
#include <stdint.h>
#include <math.h>

// Problem constants
#define B_   32
#define Q_   20
#define T_   100
#define KDIM 512          // D == H == 512 (GEMM K dim)
#define H_   512
#define N_   (B_*Q_)      // 640 sequences
#define G_   (4*H_)       // 2048 gate columns (interleaved: jp = h*4 + gate)
#define M_   (N_*T_)      // 64000 rows of the x_gates GEMM

#define LDS_   40         // xg smem row stride (fp16 elems)
#define CH     32         // xg k-chunk
#define NCHUNK (KDIM/CH)  // 16

// step kernel: CH=64 k-chunks, stride 72
#define SCH    64
#define SNCH   (KDIM/SCH) // 8
#define SSTR   72         // 64 + 8 pad

// ---------------------------------------------------------------------------
// Static device scratch
// ---------------------------------------------------------------------------
__device__ __align__(16) float  g_xg[(size_t)M_ * G_];      // interleaved gate pre-acts
__device__ __align__(16) __half gX_hi[(size_t)M_ * KDIM];   // X in plain fp16 (2-term xg split)
__device__ __align__(16) __half gWih_hi[(size_t)G_ * KDIM]; // interleaved rows
__device__ __align__(16) __half gWih_lo[(size_t)G_ * KDIM];
__device__ __align__(16) __half gWhh_hi[(size_t)G_ * KDIM]; // interleaved rows
__device__ __align__(16) __half gWhh_lo[(size_t)G_ * KDIM];
__device__ float g_biasI[G_];                               // interleaved bih+bhh
__device__ __align__(16) __half g_h_hi[2][(size_t)N_ * H_];
__device__ __align__(16) __half g_h_lo[2][(size_t)N_ * H_];
__device__ float g_c[(size_t)N_ * H_];

// ---------------------------------------------------------------------------
// PTX helpers
// ---------------------------------------------------------------------------
__device__ __forceinline__ uint32_t smem_u32_of(const void* p) {
    uint32_t a;
    asm("{ .reg .u64 t; cvta.to.shared.u64 t, %1; cvt.u32.u64 %0, t; }" : "=r"(a) : "l"(p));
    return a;
}
__device__ __forceinline__ void cp16(uint32_t dst, const void* src) {
    asm volatile("cp.async.cg.shared.global [%0], [%1], 16;" :: "r"(dst), "l"(src));
}
__device__ __forceinline__ void cp_commit() {
    asm volatile("cp.async.commit_group;" ::: "memory");
}
template<int NN> __device__ __forceinline__ void cp_wait() {
    asm volatile("cp.async.wait_group %0;" :: "n"(NN) : "memory");
}
__device__ __forceinline__ void ldm4(uint32_t addr, uint32_t* r) {
    asm volatile("ldmatrix.sync.aligned.m8n8.x4.shared.b16 {%0,%1,%2,%3}, [%4];"
        : "=r"(r[0]), "=r"(r[1]), "=r"(r[2]), "=r"(r[3]) : "r"(addr));
}
__device__ __forceinline__ void mma16816(float* c, const uint32_t* a, const uint32_t* b) {
    asm volatile("mma.sync.aligned.m16n8k16.row.col.f32.f16.f16.f32 "
        "{%0,%1,%2,%3}, {%4,%5,%6,%7}, {%8,%9}, {%0,%1,%2,%3};"
        : "+f"(c[0]), "+f"(c[1]), "+f"(c[2]), "+f"(c[3])
        : "r"(a[0]), "r"(a[1]), "r"(a[2]), "r"(a[3]), "r"(b[0]), "r"(b[1]));
}
__device__ __forceinline__ void f2split(float x, __half& hi, __half& lo) {
    hi = __float2half_rn(x);
    lo = __float2half_rn(x - __half2float(hi));
}

// ---------------------------------------------------------------------------
// Setup kernels
// ---------------------------------------------------------------------------
__global__ void init_state_kernel() {
    int idx = blockIdx.x * blockDim.x + threadIdx.x;
    if (idx < N_ * H_) {
        g_h_hi[0][idx] = __float2half_rn(0.0f);
        g_h_lo[0][idx] = __float2half_rn(0.0f);
        g_c[idx] = 0.0f;
    }
}

__global__ void conv_x_kernel(const float* __restrict__ X) {
    size_t base = ((size_t)blockIdx.x * blockDim.x + threadIdx.x) * 4;
    if (base < (size_t)M_ * KDIM) {
        float4 v = *(const float4*)(X + base);
        __half2 p0 = make_half2(__float2half_rn(v.x), __float2half_rn(v.y));
        __half2 p1 = make_half2(__float2half_rn(v.z), __float2half_rn(v.w));
        *(__half2*)(gX_hi + base)     = p0;
        *(__half2*)(gX_hi + base + 2) = p1;
    }
}

__global__ void conv_w_kernel(const float* __restrict__ Wih,
                              const float* __restrict__ Whh,
                              const float* __restrict__ bih,
                              const float* __restrict__ bhh) {
    int jp = blockIdx.x;                 // interleaved dst row 0..2047
    int gate = jp & 3, h = jp >> 2;
    int j = gate * H_ + h;               // source row
    const float* si = Wih + (size_t)j * KDIM;
    const float* sh = Whh + (size_t)j * KDIM;
    for (int k = threadIdx.x; k < KDIM; k += blockDim.x) {
        __half hi, lo;
        f2split(si[k], hi, lo);
        gWih_hi[(size_t)jp * KDIM + k] = hi; gWih_lo[(size_t)jp * KDIM + k] = lo;
        f2split(sh[k], hi, lo);
        gWhh_hi[(size_t)jp * KDIM + k] = hi; gWhh_lo[(size_t)jp * KDIM + k] = lo;
    }
    if (threadIdx.x == 0) g_biasI[jp] = bih[j] + bhh[j];
}

// ---------------------------------------------------------------------------
// x_gates GEMM: 128x128 tile, grid (16, 500), 3-stage, 2 CTAs/SM.
// A = X plain fp16; B = W_ih hi+lo. D = A*Bh + A*Bl (2-term split).
// Stage (bytes): A[128*40*2=10240] Bhi[10240] Blo[10240] = 30720.
// One sync per chunk: wait -> sync -> issue(c+2) -> compute(c).
// ---------------------------------------------------------------------------
#define XG_STAGE 30720
#define XG_SMEM  (XG_STAGE * 3)    // 92160

__global__ __launch_bounds__(256, 2)
void xg_mma_kernel() {
    extern __shared__ char smem[];
    const uint32_t sb = smem_u32_of(smem);
    __shared__ float bias_s[128];
    const int tid = threadIdx.x;
    const int j0 = blockIdx.x * 128;
    const int m0 = blockIdx.y * 128;
    if (tid < 128) bias_s[tid] = g_biasI[j0 + tid];

    const __half* Ah = gX_hi   + (size_t)m0 * KDIM;
    const __half* Bh = gWih_hi + (size_t)j0 * KDIM;
    const __half* Bl = gWih_lo + (size_t)j0 * KDIM;

    const int lane = tid & 31, wid = tid >> 5;
    const int mw = (wid & 1) * 64, nw = (wid >> 1) * 32;
    const int a_row = mw + (lane & 15);
    const int a_col = (lane >> 4) * 8;
    const int b_row = nw + ((lane >> 4) << 3) + (lane & 7);
    const int b_col = ((lane >> 3) & 1) * 8;

    float acc[4][4][4];
    #pragma unroll
    for (int a = 0; a < 4; ++a)
        #pragma unroll
        for (int b = 0; b < 4; ++b)
            #pragma unroll
            for (int d = 0; d < 4; ++d) acc[a][b][d] = 0.0f;

    #define XLOAD(stg, kc) do {                                          \
        uint32_t _b = sb + (uint32_t)(stg) * XG_STAGE;                   \
        _Pragma("unroll")                                                \
        for (int u = tid; u < 512; u += 256) {                           \
            int r_ = u >> 2, cg_ = (u & 3) * 8;                          \
            cp16(_b + (uint32_t)(r_ * LDS_ + cg_) * 2,                   \
                 Ah + (size_t)r_ * KDIM + (kc) + cg_);                   \
        }                                                                \
        _Pragma("unroll")                                                \
        for (int u = tid; u < 512; u += 256) {                           \
            int r_ = u >> 2, cg_ = (u & 3) * 8;                          \
            uint32_t d_ = _b + 10240 + (uint32_t)(r_ * LDS_ + cg_) * 2;  \
            size_t g_ = (size_t)r_ * KDIM + (kc) + cg_;                  \
            cp16(d_,         Bh + g_);                                   \
            cp16(d_ + 10240, Bl + g_);                                   \
        }                                                                \
    } while (0)

    XLOAD(0, 0);      cp_commit();
    XLOAD(1, CH);     cp_commit();

    #pragma unroll 1
    for (int c = 0; c < NCHUNK; ++c) {
        cp_wait<1>();            // stage c complete (stage c+1 may be in flight)
        __syncthreads();         // all warps done with stage (c+2)%3's old contents
        if (c + 2 < NCHUNK) XLOAD((c + 2) % 3, (c + 2) * CH);
        cp_commit();             // uniform accounting (possibly empty group)

        const uint32_t base = sb + (uint32_t)(c % 3) * XG_STAGE;
        #pragma unroll
        for (int kk = 0; kk < CH; kk += 16) {
            uint32_t ra[4][4], rbh[2][4], rbl[2][4];
            #pragma unroll
            for (int mi = 0; mi < 4; ++mi) {
                uint32_t aa = base + (uint32_t)((a_row + mi * 16) * LDS_ + kk + a_col) * 2;
                ldm4(aa, ra[mi]);
            }
            #pragma unroll
            for (int nj = 0; nj < 2; ++nj) {
                uint32_t ba = base + 10240 + (uint32_t)((b_row + nj * 16) * LDS_ + kk + b_col) * 2;
                ldm4(ba, rbh[nj]);
                ldm4(ba + 10240, rbl[nj]);
            }
            #pragma unroll
            for (int mi = 0; mi < 4; ++mi) {
                #pragma unroll
                for (int b8 = 0; b8 < 4; ++b8) {
                    const uint32_t* bh = &rbh[b8 >> 1][(b8 & 1) * 2];
                    const uint32_t* bl = &rbl[b8 >> 1][(b8 & 1) * 2];
                    mma16816(acc[mi][b8], ra[mi], bh);   // a*hi
                    mma16816(acc[mi][b8], ra[mi], bl);   // a*lo
                }
            }
        }
    }
    #undef XLOAD

    #pragma unroll
    for (int mi = 0; mi < 4; ++mi) {
        #pragma unroll
        for (int h2 = 0; h2 < 2; ++h2) {
            const int r = m0 + mw + mi * 16 + (lane >> 2) + h2 * 8;
            float* dst = g_xg + (size_t)r * G_ + j0;
            #pragma unroll
            for (int ni = 0; ni < 4; ++ni) {
                const int cc = nw + ni * 8 + (lane & 3) * 2;
                float2 v = make_float2(acc[mi][ni][h2 * 2 + 0] + bias_s[cc],
                                       acc[mi][ni][h2 * 2 + 1] + bias_s[cc + 1]);
                *(float2*)(dst + cc) = v;
            }
        }
    }
}

// ---------------------------------------------------------------------------
// Step kernel body, templated on row count MT (96 or 64). 3-term split kept
// (recurrent errors compound). CH=64, 2-stage, ONE sync per chunk.
// Stage layout (elems): Hhi[MT*72] Hlo[MT*72] Whi[64*72] Wlo[64*72]
// ---------------------------------------------------------------------------
#define STEP_SMEM 92160   // 2 stages of the MT=96 layout (worst case)

template<int MT>
__device__ __forceinline__ void step_body(
    char* smem, uint32_t sb, int tid, int j0, int hb, int n0, int t,
    float* __restrict__ out)
{
    const int MI = MT / 32;
    const int STAGE_E = 2 * MT * SSTR + 2 * 64 * SSTR;   // elems per stage
    const int STAGE_B = STAGE_E * 2;                     // bytes
    const int lane = tid & 31, wid = tid >> 5;
    const int wm = wid & 1, wn = wid >> 1;

    const int cur = t & 1, nxt = cur ^ 1;
    const __half* Hh = g_h_hi[cur] + (size_t)n0 * H_;
    const __half* Hl = g_h_lo[cur] + (size_t)n0 * H_;
    const __half* Wh = gWhh_hi + (size_t)j0 * KDIM;
    const __half* Wl = gWhh_lo + (size_t)j0 * KDIM;

    const int a_row = wm * (MI * 16) + (lane & 15);
    const int a_col = (lane >> 4) * 8;
    const int b_row = wn * 16 + ((lane >> 4) << 3) + (lane & 7);
    const int b_col = ((lane >> 3) & 1) * 8;

    float acc[MI > 2 ? 3 : 2][2][4];
    #pragma unroll
    for (int a = 0; a < MI; ++a)
        #pragma unroll
        for (int b = 0; b < 2; ++b)
            #pragma unroll
            for (int d = 0; d < 4; ++d) acc[a][b][d] = 0.0f;

    #define SLOAD(stg, kc) do {                                              \
        uint32_t _b = sb + (uint32_t)(stg) * STAGE_B;                        \
        _Pragma("unroll")                                                    \
        for (int u = tid; u < MT * 8; u += 256) {                            \
            int r_ = u >> 3, cg_ = (u & 7) * 8;                              \
            uint32_t d_ = _b + (uint32_t)(r_ * SSTR + cg_) * 2;              \
            size_t g_ = (size_t)r_ * H_ + (kc) + cg_;                        \
            cp16(d_,                 Hh + g_);                               \
            cp16(d_ + MT * SSTR * 2, Hl + g_);                               \
        }                                                                    \
        _Pragma("unroll")                                                    \
        for (int u = tid; u < 512; u += 256) {                               \
            int r_ = u >> 3, cg_ = (u & 7) * 8;                              \
            uint32_t d_ = _b + (uint32_t)(2 * MT * SSTR + r_ * SSTR + cg_) * 2; \
            size_t g_ = (size_t)r_ * KDIM + (kc) + cg_;                      \
            cp16(d_,                 Wh + g_);                               \
            cp16(d_ + 64 * SSTR * 2, Wl + g_);                               \
        }                                                                    \
    } while (0)

    SLOAD(0, 0);
    cp_commit();

    #pragma unroll 1
    for (int c = 0; c < SNCH; ++c) {
        cp_wait<0>();             // stage c complete (only group pending)
        __syncthreads();          // all warps done computing stage c-1
        if (c + 1 < SNCH) {
            SLOAD((c + 1) & 1, (c + 1) * SCH);   // overwrites buf computed at c-1: safe
            cp_commit();
        }

        const uint32_t base = sb + (uint32_t)(c & 1) * STAGE_B;
        #pragma unroll
        for (int kk = 0; kk < SCH; kk += 16) {
            uint32_t ra[MI > 2 ? 3 : 2][4], rl[MI > 2 ? 3 : 2][4], rbh[4], rbl[4];
            #pragma unroll
            for (int mi = 0; mi < MI; ++mi) {
                uint32_t aa = base + (uint32_t)((a_row + mi * 16) * SSTR + kk + a_col) * 2;
                ldm4(aa, ra[mi]);
                ldm4(aa + MT * SSTR * 2, rl[mi]);
            }
            uint32_t ba = base + (uint32_t)(2 * MT * SSTR + (b_row) * SSTR + kk + b_col) * 2;
            ldm4(ba, rbh);
            ldm4(ba + 64 * SSTR * 2, rbl);
            #pragma unroll
            for (int mi = 0; mi < MI; ++mi) {
                #pragma unroll
                for (int b8 = 0; b8 < 2; ++b8) {
                    const uint32_t* bhp = &rbh[b8 * 2];
                    const uint32_t* blp = &rbl[b8 * 2];
                    mma16816(acc[mi][b8], ra[mi], bhp);   // hi*hi
                    mma16816(acc[mi][b8], ra[mi], blp);   // hi*lo
                    mma16816(acc[mi][b8], rl[mi], bhp);   // lo*hi
                }
            }
        }
    }
    #undef SLOAD

    // all warps must finish reading stage buffers before Cs staging reuses smem
    __syncthreads();

    // stage C tile [MT][68] in smem
    float* Cs = (float*)smem;
    #pragma unroll
    for (int mi = 0; mi < MI; ++mi) {
        #pragma unroll
        for (int b8 = 0; b8 < 2; ++b8) {
            const int r = wm * (MI * 16) + mi * 16 + (lane >> 2);
            const int cc = wn * 16 + b8 * 8 + (lane & 3) * 2;
            *(float2*)&Cs[r * 68 + cc]       = make_float2(acc[mi][b8][0], acc[mi][b8][1]);
            *(float2*)&Cs[(r + 8) * 68 + cc] = make_float2(acc[mi][b8][2], acc[mi][b8][3]);
        }
    }
    __syncthreads();

    // fused LSTM cell update: MT/16 cells per thread
    const bool last = (t == T_ - 1);
    const int hl = tid & 15;
    const int rg = tid >> 4;
    #pragma unroll
    for (int e = 0; e < MT / 16; ++e) {
        const int r = rg + e * 16;
        const int gn = n0 + r;
        float4 cg = *(const float4*)&Cs[r * 68 + hl * 4];
        float4 xv = *(const float4*)(g_xg + ((size_t)gn * T_ + t) * G_ + j0 + hl * 4);
        float ig = cg.x + xv.x, fg = cg.y + xv.y;
        float gg = cg.z + xv.z, og = cg.w + xv.w;

        float is = 1.0f / (1.0f + __expf(-ig));
        float fs = 1.0f / (1.0f + __expf(-fg));
        float gt = tanhf(gg);
        float os = 1.0f / (1.0f + __expf(-og));

        const size_t ci = (size_t)gn * H_ + hb + hl;
        float c = fs * g_c[ci] + is * gt;
        g_c[ci] = c;
        float hv = os * tanhf(c);
        if (last) {
            out[ci] = hv;
        } else {
            __half hi, lo;
            f2split(hv, hi, lo);
            g_h_hi[nxt][ci] = hi;
            g_h_lo[nxt][ci] = lo;
        }
    }
}

// ---------------------------------------------------------------------------
// Step kernel: 288 CTAs = 32 jb x 9 row-tiles (2x96 + 7x64 rows), single wave.
// ---------------------------------------------------------------------------
__global__ __launch_bounds__(256, 2)
void step_mma_kernel(float* __restrict__ out, int t) {
    extern __shared__ char smem[];
    const uint32_t sb = smem_u32_of(smem);
    const int tid = threadIdx.x;
    const int bid = blockIdx.x;
    const int nt = bid >> 5;          // 0..8 (row tile)
    const int jb = bid & 31;          // 0..31 (col block)
    const int j0 = jb * 64;
    const int hb = jb * 16;

    if (nt < 2) {
        step_body<96>(smem, sb, tid, j0, hb, nt * 96, t, out);
    } else {
        step_body<64>(smem, sb, tid, j0, hb, 192 + (nt - 2) * 64, t, out);
    }
}

// ---------------------------------------------------------------------------
// Launch
// ---------------------------------------------------------------------------
extern "C" void kernel_launch(void* const* d_in, const int* in_sizes, int n_in,
                              void* d_out, int out_size)
{
    const float* X   = (const float*)d_in[0];   // [B,Q,T,D] == [N*T, D]
    const float* Wih = (const float*)d_in[1];   // [4H, D]
    const float* Whh = (const float*)d_in[2];   // [4H, H]
    const float* bih = (const float*)d_in[3];   // [4H]
    const float* bhh = (const float*)d_in[4];   // [4H]
    float* out = (float*)d_out;                 // [B,Q,H] == [N, H]

    cudaFuncSetAttribute(xg_mma_kernel,   cudaFuncAttributeMaxDynamicSharedMemorySize, XG_SMEM);
    cudaFuncSetAttribute(step_mma_kernel, cudaFuncAttributeMaxDynamicSharedMemorySize, STEP_SMEM);

    init_state_kernel<<<(N_ * H_ + 255) / 256, 256>>>();
    conv_x_kernel<<<(int)(((size_t)M_ * KDIM / 4 + 255) / 256), 256>>>(X);
    conv_w_kernel<<<G_, 256>>>(Wih, Whh, bih, bhh);

    xg_mma_kernel<<<dim3(G_ / 128, M_ / 128), 256, XG_SMEM>>>();

    for (int t = 0; t < T_; ++t) {
        step_mma_kernel<<<288, 256, STEP_SMEM>>>(out, t);
    }
}

// round 12
// speedup vs baseline: 1.5318x; 1.0377x over previous
#include <cuda_runtime.h>
#include <cuda_fp16.h>
#include <stdint.h>
#include <math.h>

// Problem constants
#define B_   32
#define Q_   20
#define T_   100
#define KDIM 512          // D == H == 512 (GEMM K dim)
#define H_   512
#define N_   (B_*Q_)      // 640 sequences
#define G_   (4*H_)       // 2048 gate columns (interleaved: jp = h*4 + gate)
#define M_   (N_*T_)      // 64000 rows of the x_gates GEMM

#define LDS_   40         // smem row stride (fp16 elems) for 32-wide k-chunks
#define CH     32         // k-chunk
#define NCHUNK (KDIM/CH)  // 16

// ---------------------------------------------------------------------------
// Static device scratch
// ---------------------------------------------------------------------------
__device__ __align__(16) float  g_xg[(size_t)M_ * G_];      // interleaved gate pre-acts
__device__ __align__(16) __half gX_hi[(size_t)M_ * KDIM];   // X in plain fp16 (2-term xg split)
__device__ __align__(16) __half gWih_hi[(size_t)G_ * KDIM]; // interleaved rows
__device__ __align__(16) __half gWih_lo[(size_t)G_ * KDIM];
__device__ __align__(16) __half gWhh_hi[(size_t)G_ * KDIM]; // interleaved rows
__device__ __align__(16) __half gWhh_lo[(size_t)G_ * KDIM];
__device__ float g_biasI[G_];                               // interleaved bih+bhh
__device__ __align__(16) __half g_h_hi[2][(size_t)N_ * H_];
__device__ __align__(16) __half g_h_lo[2][(size_t)N_ * H_];
__device__ float g_c[(size_t)N_ * H_];

// ---------------------------------------------------------------------------
// PTX helpers
// ---------------------------------------------------------------------------
__device__ __forceinline__ uint32_t smem_u32_of(const void* p) {
    uint32_t a;
    asm("{ .reg .u64 t; cvta.to.shared.u64 t, %1; cvt.u32.u64 %0, t; }" : "=r"(a) : "l"(p));
    return a;
}
__device__ __forceinline__ void cp16(uint32_t dst, const void* src) {
    asm volatile("cp.async.cg.shared.global [%0], [%1], 16;" :: "r"(dst), "l"(src));
}
__device__ __forceinline__ void cp_commit() {
    asm volatile("cp.async.commit_group;" ::: "memory");
}
template<int NN> __device__ __forceinline__ void cp_wait() {
    asm volatile("cp.async.wait_group %0;" :: "n"(NN) : "memory");
}
__device__ __forceinline__ void ldm4(uint32_t addr, uint32_t* r) {
    asm volatile("ldmatrix.sync.aligned.m8n8.x4.shared.b16 {%0,%1,%2,%3}, [%4];"
        : "=r"(r[0]), "=r"(r[1]), "=r"(r[2]), "=r"(r[3]) : "r"(addr));
}
__device__ __forceinline__ void mma16816(float* c, const uint32_t* a, const uint32_t* b) {
    asm volatile("mma.sync.aligned.m16n8k16.row.col.f32.f16.f16.f32 "
        "{%0,%1,%2,%3}, {%4,%5,%6,%7}, {%8,%9}, {%0,%1,%2,%3};"
        : "+f"(c[0]), "+f"(c[1]), "+f"(c[2]), "+f"(c[3])
        : "r"(a[0]), "r"(a[1]), "r"(a[2]), "r"(a[3]), "r"(b[0]), "r"(b[1]));
}
__device__ __forceinline__ void f2split(float x, __half& hi, __half& lo) {
    hi = __float2half_rn(x);
    lo = __float2half_rn(x - __half2float(hi));
}

// ---------------------------------------------------------------------------
// Setup kernels
// ---------------------------------------------------------------------------
__global__ void init_state_kernel() {
    int idx = blockIdx.x * blockDim.x + threadIdx.x;
    if (idx < N_ * H_) {
        g_h_hi[0][idx] = __float2half_rn(0.0f);
        g_h_lo[0][idx] = __float2half_rn(0.0f);
        g_c[idx] = 0.0f;
    }
}

__global__ void conv_x_kernel(const float* __restrict__ X) {
    size_t base = ((size_t)blockIdx.x * blockDim.x + threadIdx.x) * 4;
    if (base < (size_t)M_ * KDIM) {
        float4 v = *(const float4*)(X + base);
        __half2 p0 = make_half2(__float2half_rn(v.x), __float2half_rn(v.y));
        __half2 p1 = make_half2(__float2half_rn(v.z), __float2half_rn(v.w));
        *(__half2*)(gX_hi + base)     = p0;
        *(__half2*)(gX_hi + base + 2) = p1;
    }
}

__global__ void conv_w_kernel(const float* __restrict__ Wih,
                              const float* __restrict__ Whh,
                              const float* __restrict__ bih,
                              const float* __restrict__ bhh) {
    int jp = blockIdx.x;                 // interleaved dst row 0..2047
    int gate = jp & 3, h = jp >> 2;
    int j = gate * H_ + h;               // source row
    const float* si = Wih + (size_t)j * KDIM;
    const float* sh = Whh + (size_t)j * KDIM;
    for (int k = threadIdx.x; k < KDIM; k += blockDim.x) {
        __half hi, lo;
        f2split(si[k], hi, lo);
        gWih_hi[(size_t)jp * KDIM + k] = hi; gWih_lo[(size_t)jp * KDIM + k] = lo;
        f2split(sh[k], hi, lo);
        gWhh_hi[(size_t)jp * KDIM + k] = hi; gWhh_lo[(size_t)jp * KDIM + k] = lo;
    }
    if (threadIdx.x == 0) g_biasI[jp] = bih[j] + bhh[j];
}

// ---------------------------------------------------------------------------
// x_gates GEMM: 128x128 tile, grid (16, 500), 3-stage, 2 CTAs/SM (as R11).
// A = X plain fp16; B = W_ih hi+lo. D = A*Bh + A*Bl (2-term split).
// ---------------------------------------------------------------------------
#define XG_STAGE 30720
#define XG_SMEM  (XG_STAGE * 3)    // 92160

__global__ __launch_bounds__(256, 2)
void xg_mma_kernel() {
    extern __shared__ char smem[];
    const uint32_t sb = smem_u32_of(smem);
    __shared__ float bias_s[128];
    const int tid = threadIdx.x;
    const int j0 = blockIdx.x * 128;
    const int m0 = blockIdx.y * 128;
    if (tid < 128) bias_s[tid] = g_biasI[j0 + tid];

    const __half* Ah = gX_hi   + (size_t)m0 * KDIM;
    const __half* Bh = gWih_hi + (size_t)j0 * KDIM;
    const __half* Bl = gWih_lo + (size_t)j0 * KDIM;

    const int lane = tid & 31, wid = tid >> 5;
    const int mw = (wid & 1) * 64, nw = (wid >> 1) * 32;
    const int a_row = mw + (lane & 15);
    const int a_col = (lane >> 4) * 8;
    const int b_row = nw + ((lane >> 4) << 3) + (lane & 7);
    const int b_col = ((lane >> 3) & 1) * 8;

    float acc[4][4][4];
    #pragma unroll
    for (int a = 0; a < 4; ++a)
        #pragma unroll
        for (int b = 0; b < 4; ++b)
            #pragma unroll
            for (int d = 0; d < 4; ++d) acc[a][b][d] = 0.0f;

    #define XLOAD(stg, kc) do {                                          \
        uint32_t _b = sb + (uint32_t)(stg) * XG_STAGE;                   \
        _Pragma("unroll")                                                \
        for (int u = tid; u < 512; u += 256) {                           \
            int r_ = u >> 2, cg_ = (u & 3) * 8;                          \
            cp16(_b + (uint32_t)(r_ * LDS_ + cg_) * 2,                   \
                 Ah + (size_t)r_ * KDIM + (kc) + cg_);                   \
        }                                                                \
        _Pragma("unroll")                                                \
        for (int u = tid; u < 512; u += 256) {                           \
            int r_ = u >> 2, cg_ = (u & 3) * 8;                          \
            uint32_t d_ = _b + 10240 + (uint32_t)(r_ * LDS_ + cg_) * 2;  \
            size_t g_ = (size_t)r_ * KDIM + (kc) + cg_;                  \
            cp16(d_,         Bh + g_);                                   \
            cp16(d_ + 10240, Bl + g_);                                   \
        }                                                                \
    } while (0)

    XLOAD(0, 0);      cp_commit();
    XLOAD(1, CH);     cp_commit();

    #pragma unroll 1
    for (int c = 0; c < NCHUNK; ++c) {
        cp_wait<1>();
        __syncthreads();
        if (c + 2 < NCHUNK) XLOAD((c + 2) % 3, (c + 2) * CH);
        cp_commit();

        const uint32_t base = sb + (uint32_t)(c % 3) * XG_STAGE;
        #pragma unroll
        for (int kk = 0; kk < CH; kk += 16) {
            uint32_t ra[4][4], rbh[2][4], rbl[2][4];
            #pragma unroll
            for (int mi = 0; mi < 4; ++mi) {
                uint32_t aa = base + (uint32_t)((a_row + mi * 16) * LDS_ + kk + a_col) * 2;
                ldm4(aa, ra[mi]);
            }
            #pragma unroll
            for (int nj = 0; nj < 2; ++nj) {
                uint32_t ba = base + 10240 + (uint32_t)((b_row + nj * 16) * LDS_ + kk + b_col) * 2;
                ldm4(ba, rbh[nj]);
                ldm4(ba + 10240, rbl[nj]);
            }
            #pragma unroll
            for (int mi = 0; mi < 4; ++mi) {
                #pragma unroll
                for (int b8 = 0; b8 < 4; ++b8) {
                    const uint32_t* bh = &rbh[b8 >> 1][(b8 & 1) * 2];
                    const uint32_t* bl = &rbl[b8 >> 1][(b8 & 1) * 2];
                    mma16816(acc[mi][b8], ra[mi], bh);   // a*hi
                    mma16816(acc[mi][b8], ra[mi], bl);   // a*lo
                }
            }
        }
    }
    #undef XLOAD

    #pragma unroll
    for (int mi = 0; mi < 4; ++mi) {
        #pragma unroll
        for (int h2 = 0; h2 < 2; ++h2) {
            const int r = m0 + mw + mi * 16 + (lane >> 2) + h2 * 8;
            float* dst = g_xg + (size_t)r * G_ + j0;
            #pragma unroll
            for (int ni = 0; ni < 4; ++ni) {
                const int cc = nw + ni * 8 + (lane & 3) * 2;
                float2 v = make_float2(acc[mi][ni][h2 * 2 + 0] + bias_s[cc],
                                       acc[mi][ni][h2 * 2 + 1] + bias_s[cc + 1]);
                *(float2*)(dst + cc) = v;
            }
        }
    }
}

// ---------------------------------------------------------------------------
// Step kernel body, templated on row count MT (96 or 64). 3-term split.
// CH=32, 3-stage pipeline + xg tile prefetched to smem (in stage-0's group).
// Stage (elems): Hhi[MT*40] Hlo[MT*40] Whi[64*40] Wlo[64*40]
// smem map: [0 .. 3*STAGE_B)  pipeline stages (stage 0 reused for C staging)
//           [3*STAGE_B .. +MT*64*4)  xg tile [MT][64] fp32
// ---------------------------------------------------------------------------
#define STEP_SMEM (3 * ((2*96*LDS_ + 2*64*LDS_) * 2) + 96*64*4)   // 101376

template<int MT>
__device__ __forceinline__ void step_body(
    char* smem, uint32_t sb, int tid, int j0, int hb, int n0, int t,
    float* __restrict__ out)
{
    const int MI = MT / 32;
    const int STAGE_E = 2 * MT * LDS_ + 2 * 64 * LDS_;   // elems per stage
    const int STAGE_B = STAGE_E * 2;                     // bytes
    const int XGOFF   = 3 * STAGE_B;                     // xg tile offset (bytes)
    const int lane = tid & 31, wid = tid >> 5;
    const int wm = wid & 1, wn = wid >> 1;

    const int cur = t & 1, nxt = cur ^ 1;
    const __half* Hh = g_h_hi[cur] + (size_t)n0 * H_;
    const __half* Hl = g_h_lo[cur] + (size_t)n0 * H_;
    const __half* Wh = gWhh_hi + (size_t)j0 * KDIM;
    const __half* Wl = gWhh_lo + (size_t)j0 * KDIM;

    const int a_row = wm * (MI * 16) + (lane & 15);
    const int a_col = (lane >> 4) * 8;
    const int b_row = wn * 16 + ((lane >> 4) << 3) + (lane & 7);
    const int b_col = ((lane >> 3) & 1) * 8;

    float acc[MI > 2 ? 3 : 2][2][4];
    #pragma unroll
    for (int a = 0; a < MI; ++a)
        #pragma unroll
        for (int b = 0; b < 2; ++b)
            #pragma unroll
            for (int d = 0; d < 4; ++d) acc[a][b][d] = 0.0f;

    // chunk loader: MT rows h (hi+lo) + 64 rows W (hi+lo), 32 k each
    #define SLOAD(stg, kc) do {                                              \
        uint32_t _b = sb + (uint32_t)(stg) * STAGE_B;                        \
        _Pragma("unroll")                                                    \
        for (int u = tid; u < MT * 4; u += 256) {                            \
            int r_ = u >> 2, cg_ = (u & 3) * 8;                              \
            uint32_t d_ = _b + (uint32_t)(r_ * LDS_ + cg_) * 2;              \
            size_t g_ = (size_t)r_ * H_ + (kc) + cg_;                        \
            cp16(d_,                 Hh + g_);                               \
            cp16(d_ + MT * LDS_ * 2, Hl + g_);                               \
        }                                                                    \
        _Pragma("unroll")                                                    \
        for (int u = tid; u < 256; u += 256) {                               \
            int r_ = u >> 2, cg_ = (u & 3) * 8;                              \
            uint32_t d_ = _b + (uint32_t)(2 * MT * LDS_ + r_ * LDS_ + cg_) * 2; \
            size_t g_ = (size_t)r_ * KDIM + (kc) + cg_;                      \
            cp16(d_,                 Wh + g_);                               \
            cp16(d_ + 64 * LDS_ * 2, Wl + g_);                               \
        }                                                                    \
    } while (0)

    // group G0: stage 0 + the whole xg tile for this (tile, t)
    SLOAD(0, 0);
    #pragma unroll
    for (int u = tid; u < MT * 16; u += 256) {
        int r = u >> 4, cg = (u & 15) * 4;
        cp16(sb + XGOFF + (uint32_t)(r * 64 + cg) * 4,
             g_xg + ((size_t)(n0 + r) * T_ + t) * G_ + j0 + cg);
    }
    cp_commit();
    // group G1: stage 1
    SLOAD(1, CH);
    cp_commit();

    #pragma unroll 1
    for (int c = 0; c < NCHUNK; ++c) {
        cp_wait<1>();             // stage c (+xg if c==0) complete
        __syncthreads();          // all warps done with the buffer being refilled
        if (c + 2 < NCHUNK) SLOAD((c + 2) % 3, (c + 2) * CH);
        cp_commit();              // uniform accounting

        const uint32_t base = sb + (uint32_t)(c % 3) * STAGE_B;
        #pragma unroll
        for (int kk = 0; kk < CH; kk += 16) {
            uint32_t ra[MI > 2 ? 3 : 2][4], rl[MI > 2 ? 3 : 2][4], rbh[4], rbl[4];
            #pragma unroll
            for (int mi = 0; mi < MI; ++mi) {
                uint32_t aa = base + (uint32_t)((a_row + mi * 16) * LDS_ + kk + a_col) * 2;
                ldm4(aa, ra[mi]);
                ldm4(aa + MT * LDS_ * 2, rl[mi]);
            }
            uint32_t ba = base + (uint32_t)(2 * MT * LDS_ + b_row * LDS_ + kk + b_col) * 2;
            ldm4(ba, rbh);
            ldm4(ba + 64 * LDS_ * 2, rbl);
            #pragma unroll
            for (int mi = 0; mi < MI; ++mi) {
                #pragma unroll
                for (int b8 = 0; b8 < 2; ++b8) {
                    const uint32_t* bhp = &rbh[b8 * 2];
                    const uint32_t* blp = &rbl[b8 * 2];
                    mma16816(acc[mi][b8], ra[mi], bhp);   // hi*hi
                    mma16816(acc[mi][b8], ra[mi], blp);   // hi*lo
                    mma16816(acc[mi][b8], rl[mi], bhp);   // lo*hi
                }
            }
        }
    }
    #undef SLOAD

    // all warps done reading stage buffers before C staging reuses stage 0
    __syncthreads();

    // stage C tile [MT][68] in smem (stage-0/1 region; xg tile untouched)
    float* Cs = (float*)smem;
    #pragma unroll
    for (int mi = 0; mi < MI; ++mi) {
        #pragma unroll
        for (int b8 = 0; b8 < 2; ++b8) {
            const int r = wm * (MI * 16) + mi * 16 + (lane >> 2);
            const int cc = wn * 16 + b8 * 8 + (lane & 3) * 2;
            *(float2*)&Cs[r * 68 + cc]       = make_float2(acc[mi][b8][0], acc[mi][b8][1]);
            *(float2*)&Cs[(r + 8) * 68 + cc] = make_float2(acc[mi][b8][2], acc[mi][b8][3]);
        }
    }
    __syncthreads();

    // fused LSTM cell update: MT/16 cells per thread; xg from smem
    const float* xgS = (const float*)(smem + XGOFF);
    const bool last = (t == T_ - 1);
    const int hl = tid & 15;
    const int rg = tid >> 4;
    #pragma unroll
    for (int e = 0; e < MT / 16; ++e) {
        const int r = rg + e * 16;
        const int gn = n0 + r;
        float4 cg = *(const float4*)&Cs[r * 68 + hl * 4];
        float4 xv = *(const float4*)&xgS[r * 64 + hl * 4];
        float ig = cg.x + xv.x, fg = cg.y + xv.y;
        float gg = cg.z + xv.z, og = cg.w + xv.w;

        float is = 1.0f / (1.0f + __expf(-ig));
        float fs = 1.0f / (1.0f + __expf(-fg));
        float gt = tanhf(gg);
        float os = 1.0f / (1.0f + __expf(-og));

        const size_t ci = (size_t)gn * H_ + hb + hl;
        float c = fs * g_c[ci] + is * gt;
        g_c[ci] = c;
        float hv = os * tanhf(c);
        if (last) {
            out[ci] = hv;
        } else {
            __half hi, lo;
            f2split(hv, hi, lo);
            g_h_hi[nxt][ci] = hi;
            g_h_lo[nxt][ci] = lo;
        }
    }
}

// ---------------------------------------------------------------------------
// Step kernel: 288 CTAs = 32 jb x 9 row-tiles (2x96 + 7x64 rows), single wave.
// ---------------------------------------------------------------------------
__global__ __launch_bounds__(256, 2)
void step_mma_kernel(float* __restrict__ out, int t) {
    extern __shared__ char smem[];
    const uint32_t sb = smem_u32_of(smem);
    const int tid = threadIdx.x;
    const int bid = blockIdx.x;
    const int nt = bid >> 5;          // 0..8 (row tile)
    const int jb = bid & 31;          // 0..31 (col block)
    const int j0 = jb * 64;
    const int hb = jb * 16;

    if (nt < 2) {
        step_body<96>(smem, sb, tid, j0, hb, nt * 96, t, out);
    } else {
        step_body<64>(smem, sb, tid, j0, hb, 192 + (nt - 2) * 64, t, out);
    }
}

// ---------------------------------------------------------------------------
// Launch
// ---------------------------------------------------------------------------
extern "C" void kernel_launch(void* const* d_in, const int* in_sizes, int n_in,
                              void* d_out, int out_size)
{
    const float* X   = (const float*)d_in[0];   // [B,Q,T,D] == [N*T, D]
    const float* Wih = (const float*)d_in[1];   // [4H, D]
    const float* Whh = (const float*)d_in[2];   // [4H, H]
    const float* bih = (const float*)d_in[3];   // [4H]
    const float* bhh = (const float*)d_in[4];   // [4H]
    float* out = (float*)d_out;                 // [B,Q,H] == [N, H]

    cudaFuncSetAttribute(xg_mma_kernel,   cudaFuncAttributeMaxDynamicSharedMemorySize, XG_SMEM);
    cudaFuncSetAttribute(step_mma_kernel, cudaFuncAttributeMaxDynamicSharedMemorySize, STEP_SMEM);

    init_state_kernel<<<(N_ * H_ + 255) / 256, 256>>>();
    conv_x_kernel<<<(int)(((size_t)M_ * KDIM / 4 + 255) / 256), 256>>>(X);
    conv_w_kernel<<<G_, 256>>>(Wih, Whh, bih, bhh);

    xg_mma_kernel<<<dim3(G_ / 128, M_ / 128), 256, XG_SMEM>>>();

    for (int t = 0; t < T_; ++t) {
        step_mma_kernel<<<288, 256, STEP_SMEM>>>(out, t);
    }
}